// round 11
// baseline (speedup 1.0000x reference)
#include <cuda_runtime.h>
#include <cuda_bf16.h>
#include <cstdint>

#define F_IN 128
#define F_OUT 64
#define MAX_NODES 50000

// Scratch (no runtime allocation allowed)
__device__ float g_hw[(size_t)MAX_NODES * F_OUT];   // h @ (W0+W1), [N][64]
__device__ float2 g_whl[F_IN][F_OUT];               // (hi, lo) tf32 split of W0+W1

// ---------------------------------------------------------------------------
// TF32 helpers
// ---------------------------------------------------------------------------
__device__ __forceinline__ unsigned cvt_tf32(float x) {
    unsigned r;
    asm("cvt.rna.tf32.f32 %0, %1;" : "=r"(r) : "f"(x));
    return r;
}

#define MMA_TF32(d, a0, a1, a2, a3, b0, b1)                                  \
    asm("mma.sync.aligned.m16n8k8.row.col.f32.tf32.tf32.f32 "                \
        "{%0,%1,%2,%3}, {%4,%5,%6,%7}, {%8,%9}, {%0,%1,%2,%3};"              \
        : "+f"(d[0]), "+f"(d[1]), "+f"(d[2]), "+f"(d[3])                     \
        : "r"(a0), "r"(a1), "r"(a2), "r"(a3), "r"(b0), "r"(b1))

// ---------------------------------------------------------------------------
// Kernel 0: prep — W0+W1 summed and split into tf32 (hi, lo) pairs, once.
// ---------------------------------------------------------------------------
__global__ void prep_kernel(const float* __restrict__ w) {
    int i = blockIdx.x * blockDim.x + threadIdx.x;   // 0 .. 8191
    if (i < F_IN * F_OUT) {
        float s = w[i] + w[F_IN * F_OUT + i];
        float hi = __uint_as_float(cvt_tf32(s));
        ((float2*)g_whl)[i] = make_float2(hi, s - hi);
    }
}

// ---------------------------------------------------------------------------
// Kernel 1: TF32 tensor-core GEMM + bias-init (3xTF32, fp32 accuracy)
//   g_hw[N,64] = h[N,128] @ (W0+W1) ;  out[N,64] = bias
// Block: 64 rows x 64 cols, 128 threads (4 warps). Full A tile staged once
// (1 syncthreads); B fragments read directly from L1-resident g_whl via
// LDG.64 (hi+lo in one load). A-frag LDS banks 4g+t: conflict-free.
// ---------------------------------------------------------------------------
#define GR 64
#define HS_S 132   // A row stride in floats (132 mod 32 = 4 -> distinct banks)
__global__ void __launch_bounds__(128) gemm_tc_kernel(
        const float* __restrict__ h,
        const float* __restrict__ bias,
        float* __restrict__ out,
        int n_nodes) {
    __shared__ __align__(16) float hs[GR][HS_S];   // 33.8 KB: full A tile [row][k]

    int tid  = threadIdx.x;
    int lane = tid & 31;
    int warp = tid >> 5;
    int g = lane >> 2;      // 0..7
    int t = lane & 3;       // 0..3
    int row0 = blockIdx.x * GR;
    int wr0  = warp * 16;

    // Stage full A tile: 64 rows x 128 k = 2048 float4
    #pragma unroll
    for (int i = tid; i < GR * (F_IN / 4); i += 128) {
        int r = i >> 5;          // row
        int c = i & 31;          // float4 idx along k
        float4 v = make_float4(0.f, 0.f, 0.f, 0.f);
        if (row0 + r < n_nodes)
            v = ((const float4*)(h + (size_t)(row0 + r) * F_IN))[c];
        hs[r][4 * c + 0] = v.x;
        hs[r][4 * c + 1] = v.y;
        hs[r][4 * c + 2] = v.z;
        hs[r][4 * c + 3] = v.w;
    }
    __syncthreads();

    float acc[8][4];
    #pragma unroll
    for (int nt = 0; nt < 8; nt++)
        #pragma unroll
        for (int i = 0; i < 4; i++) acc[nt][i] = 0.0f;

    #pragma unroll
    for (int ks = 0; ks < F_IN; ks += 8) {
        float af0 = hs[wr0 + g][ks + t];
        float af1 = hs[wr0 + g + 8][ks + t];
        float af2 = hs[wr0 + g][ks + t + 4];
        float af3 = hs[wr0 + g + 8][ks + t + 4];
        unsigned ah0 = cvt_tf32(af0), ah1 = cvt_tf32(af1);
        unsigned ah2 = cvt_tf32(af2), ah3 = cvt_tf32(af3);
        unsigned al0 = __float_as_uint(af0 - __uint_as_float(ah0));
        unsigned al1 = __float_as_uint(af1 - __uint_as_float(ah1));
        unsigned al2 = __float_as_uint(af2 - __uint_as_float(ah2));
        unsigned al3 = __float_as_uint(af3 - __uint_as_float(ah3));

        #pragma unroll
        for (int nt = 0; nt < 8; nt++) {
            int n = 8 * nt + g;
            float2 b0p = __ldg((const float2*)&g_whl[ks + t][n]);
            float2 b1p = __ldg((const float2*)&g_whl[ks + t + 4][n]);
            unsigned bh0 = __float_as_uint(b0p.x), bl0 = __float_as_uint(b0p.y);
            unsigned bh1 = __float_as_uint(b1p.x), bl1 = __float_as_uint(b1p.y);
            MMA_TF32(acc[nt], ah0, ah1, ah2, ah3, bh0, bh1);
            MMA_TF32(acc[nt], ah0, ah1, ah2, ah3, bl0, bl1);
            MMA_TF32(acc[nt], al0, al1, al2, al3, bh0, bh1);
        }
    }

    int r1 = row0 + wr0 + g;
    int r2 = r1 + 8;
    #pragma unroll
    for (int nt = 0; nt < 8; nt++) {
        int c = 8 * nt + 2 * t;
        float2 bv = make_float2(__ldg(bias + c), __ldg(bias + c + 1));
        if (r1 < n_nodes) {
            *(float2*)&g_hw[(size_t)r1 * F_OUT + c] = make_float2(acc[nt][0], acc[nt][1]);
            *(float2*)&out[(size_t)r1 * F_OUT + c] = bv;
        }
        if (r2 < n_nodes) {
            *(float2*)&g_hw[(size_t)r2 * F_OUT + c] = make_float2(acc[nt][2], acc[nt][3]);
            *(float2*)&out[(size_t)r2 * F_OUT + c] = bv;
        }
    }
}

// ---------------------------------------------------------------------------
// Kernel 2: edge phase — FROZEN at the measured optimum (round 8): 4 edges
// per warp, 2 per 16-lane group (2x MLP at ~84% occupancy). softmax w/o
// max-sub (O(1) inputs), gather hw[src], red.v4 into out[dst]. __ldcs stream.
// ---------------------------------------------------------------------------
__global__ void edge_kernel(const float* __restrict__ ef,
                            const int* __restrict__ src,
                            const int* __restrict__ dst,
                            float* __restrict__ out,
                            int n_edges) {
    int gw   = (blockIdx.x * blockDim.x + threadIdx.x) >> 5;
    int lane = threadIdx.x & 31;
    int grp  = lane >> 4;
    int sl   = lane & 15;

    int eA = 4 * gw + grp;
    int eB = eA + 2;
    bool vA = (eA < n_edges), vB = (eB < n_edges);
    int ecA = vA ? eA : 0;
    int ecB = vB ? eB : 0;

    int siA = __ldg(src + ecA), diA = __ldg(dst + ecA);
    int siB = __ldg(src + ecB), diB = __ldg(dst + ecB);

    const float4* ef4 = (const float4*)ef;
    float4 a = __ldcs(ef4 + (size_t)ecA * (F_OUT / 4) + sl);
    float4 b = __ldcs(ef4 + (size_t)ecB * (F_OUT / 4) + sl);

    const float4* hw4 = (const float4*)g_hw;
    float4 hA = __ldg(hw4 + (size_t)siA * (F_OUT / 4) + sl);
    float4 hB = __ldg(hw4 + (size_t)siB * (F_OUT / 4) + sl);

    float a0 = __expf(a.x), a1 = __expf(a.y), a2 = __expf(a.z), a3 = __expf(a.w);
    float b0 = __expf(b.x), b1 = __expf(b.y), b2 = __expf(b.z), b3 = __expf(b.w);
    float sA = a0 + a1 + a2 + a3;
    float sB = b0 + b1 + b2 + b3;
    #pragma unroll
    for (int o = 8; o; o >>= 1) {
        sA += __shfl_xor_sync(0xffffffffu, sA, o);
        sB += __shfl_xor_sync(0xffffffffu, sB, o);
    }
    float iA = __fdividef(1.0f, sA);
    float iB = __fdividef(1.0f, sB);

    if (vA) {
        float* p = out + (size_t)diA * F_OUT + 4 * sl;
        asm volatile("red.global.add.v4.f32 [%0], {%1, %2, %3, %4};"
                     :: "l"(p), "f"(hA.x * a0 * iA), "f"(hA.y * a1 * iA),
                        "f"(hA.z * a2 * iA), "f"(hA.w * a3 * iA) : "memory");
    }
    if (vB) {
        float* p = out + (size_t)diB * F_OUT + 4 * sl;
        asm volatile("red.global.add.v4.f32 [%0], {%1, %2, %3, %4};"
                     :: "l"(p), "f"(hB.x * b0 * iB), "f"(hB.y * b1 * iB),
                        "f"(hB.z * b2 * iB), "f"(hB.w * b3 * iB) : "memory");
    }
}

// ---------------------------------------------------------------------------
extern "C" void kernel_launch(void* const* d_in, const int* in_sizes, int n_in,
                              void* d_out, int out_size) {
    const float* h    = (const float*)d_in[0];
    const float* ef   = (const float*)d_in[1];
    const float* w    = (const float*)d_in[2];
    const float* bias = (const float*)d_in[3];
    const int*   src  = (const int*)d_in[4];
    const int*   dst  = (const int*)d_in[5];
    float* out = (float*)d_out;

    int n_nodes = in_sizes[0] / F_IN;
    int n_edges = in_sizes[4];

    prep_kernel<<<(F_IN * F_OUT + 255) / 256, 256>>>(w);
    gemm_tc_kernel<<<(n_nodes + GR - 1) / GR, 128>>>(h, bias, out, n_nodes);

    int warps  = (n_edges + 3) / 4;
    int blocks = (warps * 32 + 255) / 256;
    edge_kernel<<<blocks, 256>>>(ef, src, dst, out, n_edges);
}

// round 12
// speedup vs baseline: 1.2740x; 1.2740x over previous
#include <cuda_runtime.h>
#include <cuda_bf16.h>
#include <cstdint>

#define F_IN 128
#define F_OUT 64
#define MAX_NODES 50000

// Scratch (no runtime allocation allowed)
__device__ float g_hw[(size_t)MAX_NODES * F_OUT]; // h @ (W0+W1), [N][64]

// ---------------------------------------------------------------------------
// TF32 helpers
// ---------------------------------------------------------------------------
__device__ __forceinline__ unsigned cvt_tf32(float x) {
    unsigned r;
    asm("cvt.rna.tf32.f32 %0, %1;" : "=r"(r) : "f"(x));
    return r;
}

#define MMA_TF32(d, a0, a1, a2, a3, b0, b1)                                  \
    asm("mma.sync.aligned.m16n8k8.row.col.f32.tf32.tf32.f32 "                \
        "{%0,%1,%2,%3}, {%4,%5,%6,%7}, {%8,%9}, {%0,%1,%2,%3};"              \
        : "+f"(d[0]), "+f"(d[1]), "+f"(d[2]), "+f"(d[3])                     \
        : "r"(a0), "r"(a1), "r"(a2), "r"(a3), "r"(b0), "r"(b1))

// ---------------------------------------------------------------------------
// Kernel 1: fused TF32 tensor-core GEMM + bias-init (3xTF32, fp32 accuracy)
//   g_hw[N,64] = h[N,128] @ (W0+W1) ;  out[N,64] = bias
// Round-8 structure (smem-staged W — proven fastest), widened to GR=128 rows
// per block / 256 threads: halves the per-block redundant W-split work and
// block count chip-wide. smem: 18.4 + 9.2 + 9.2 KB = 36.9 KB (static-OK).
// ---------------------------------------------------------------------------
#define GR 128
#define KC 32
#define HS_S 36
#define WS_S 72
__global__ void __launch_bounds__(256) gemm_tc_kernel(
        const float* __restrict__ h,
        const float* __restrict__ w,
        const float* __restrict__ bias,
        float* __restrict__ out,
        int n_nodes) {
    __shared__ __align__(16) float hs[GR][HS_S];   // 18.4 KB: A chunk [row][k]
    __shared__ __align__(16) float wh[KC][WS_S];   // 9.2 KB: Wsum hi [k][n]
    __shared__ __align__(16) float wl[KC][WS_S];   // 9.2 KB: Wsum lo [k][n]
    __shared__ __align__(16) float bs[F_OUT];

    int tid  = threadIdx.x;
    int lane = tid & 31;
    int warp = tid >> 5;     // 0..7
    int g = lane >> 2;       // 0..7
    int t = lane & 3;        // 0..3
    int row0 = blockIdx.x * GR;
    int wr0  = warp * 16;    // warp's row offset within tile

    if (tid < F_OUT) bs[tid] = bias[tid];

    float acc[8][4];
    #pragma unroll
    for (int nt = 0; nt < 8; nt++)
        #pragma unroll
        for (int i = 0; i < 4; i++) acc[nt][i] = 0.0f;

    #pragma unroll
    for (int chunk = 0; chunk < F_IN / KC; chunk++) {
        int k0 = chunk * KC;
        __syncthreads();    // previous chunk's consumers done (1st iter: bs)

        // Stage A chunk: 128 rows x 32 k = 1024 float4 (4 per thread)
        #pragma unroll
        for (int i = tid; i < GR * (KC / 4); i += 256) {
            int r = i >> 3;          // row (8 float4 per row)
            int c = i & 7;           // float4 idx within row
            float4 v = make_float4(0.f, 0.f, 0.f, 0.f);
            if (row0 + r < n_nodes)
                v = ((const float4*)(h + (size_t)(row0 + r) * F_IN + k0))[c];
            hs[r][4 * c + 0] = v.x;
            hs[r][4 * c + 1] = v.y;
            hs[r][4 * c + 2] = v.z;
            hs[r][4 * c + 3] = v.w;
        }

        // Stage W chunk: wsum = W0+W1, split hi/lo (512 float4, 2 per thread)
        #pragma unroll
        for (int i = tid; i < KC * (F_OUT / 4); i += 256) {
            int k = i >> 4;          // k within chunk
            int q = i & 15;          // float4 idx
            const float4* w0 = (const float4*)(w + (size_t)(k0 + k) * F_OUT);
            const float4* w1 = (const float4*)(w + (size_t)F_IN * F_OUT + (size_t)(k0 + k) * F_OUT);
            float4 s0 = w0[q], s1 = w1[q];
            float s[4] = {s0.x + s1.x, s0.y + s1.y, s0.z + s1.z, s0.w + s1.w};
            #pragma unroll
            for (int j = 0; j < 4; j++) {
                float hi = __uint_as_float(cvt_tf32(s[j]));
                wh[k][4 * q + j] = hi;
                wl[k][4 * q + j] = s[j] - hi;
            }
        }
        __syncthreads();

        // Compute: 4 k-steps of 8
        #pragma unroll
        for (int ks = 0; ks < KC; ks += 8) {
            float af0 = hs[wr0 + g][ks + t];
            float af1 = hs[wr0 + g + 8][ks + t];
            float af2 = hs[wr0 + g][ks + t + 4];
            float af3 = hs[wr0 + g + 8][ks + t + 4];
            unsigned ah0 = cvt_tf32(af0), ah1 = cvt_tf32(af1);
            unsigned ah2 = cvt_tf32(af2), ah3 = cvt_tf32(af3);
            unsigned al0 = __float_as_uint(af0 - __uint_as_float(ah0));
            unsigned al1 = __float_as_uint(af1 - __uint_as_float(ah1));
            unsigned al2 = __float_as_uint(af2 - __uint_as_float(ah2));
            unsigned al3 = __float_as_uint(af3 - __uint_as_float(ah3));

            #pragma unroll
            for (int nt = 0; nt < 8; nt++) {
                int n = 8 * nt + g;
                unsigned bh0 = __float_as_uint(wh[ks + t][n]);
                unsigned bh1 = __float_as_uint(wh[ks + t + 4][n]);
                unsigned bl0 = __float_as_uint(wl[ks + t][n]);
                unsigned bl1 = __float_as_uint(wl[ks + t + 4][n]);
                MMA_TF32(acc[nt], ah0, ah1, ah2, ah3, bh0, bh1);
                MMA_TF32(acc[nt], ah0, ah1, ah2, ah3, bl0, bl1);
                MMA_TF32(acc[nt], al0, al1, al2, al3, bh0, bh1);
            }
        }
    }

    int r1 = row0 + wr0 + g;
    int r2 = r1 + 8;
    #pragma unroll
    for (int nt = 0; nt < 8; nt++) {
        int c = 8 * nt + 2 * t;
        float2 bv = make_float2(bs[c], bs[c + 1]);
        if (r1 < n_nodes) {
            *(float2*)&g_hw[(size_t)r1 * F_OUT + c] = make_float2(acc[nt][0], acc[nt][1]);
            *(float2*)&out[(size_t)r1 * F_OUT + c] = bv;
        }
        if (r2 < n_nodes) {
            *(float2*)&g_hw[(size_t)r2 * F_OUT + c] = make_float2(acc[nt][2], acc[nt][3]);
            *(float2*)&out[(size_t)r2 * F_OUT + c] = bv;
        }
    }
}

// ---------------------------------------------------------------------------
// Kernel 2: edge phase — FROZEN at measured L2 roofline (round 8): 4 edges
// per warp, 2 per 16-lane group. L2 traffic ~615MB -> ~53us is the floor.
// ---------------------------------------------------------------------------
__global__ void edge_kernel(const float* __restrict__ ef,
                            const int* __restrict__ src,
                            const int* __restrict__ dst,
                            float* __restrict__ out,
                            int n_edges) {
    int gw   = (blockIdx.x * blockDim.x + threadIdx.x) >> 5;
    int lane = threadIdx.x & 31;
    int grp  = lane >> 4;
    int sl   = lane & 15;

    int eA = 4 * gw + grp;
    int eB = eA + 2;
    bool vA = (eA < n_edges), vB = (eB < n_edges);
    int ecA = vA ? eA : 0;
    int ecB = vB ? eB : 0;

    int siA = __ldg(src + ecA), diA = __ldg(dst + ecA);
    int siB = __ldg(src + ecB), diB = __ldg(dst + ecB);

    const float4* ef4 = (const float4*)ef;
    float4 a = __ldcs(ef4 + (size_t)ecA * (F_OUT / 4) + sl);
    float4 b = __ldcs(ef4 + (size_t)ecB * (F_OUT / 4) + sl);

    const float4* hw4 = (const float4*)g_hw;
    float4 hA = __ldg(hw4 + (size_t)siA * (F_OUT / 4) + sl);
    float4 hB = __ldg(hw4 + (size_t)siB * (F_OUT / 4) + sl);

    float a0 = __expf(a.x), a1 = __expf(a.y), a2 = __expf(a.z), a3 = __expf(a.w);
    float b0 = __expf(b.x), b1 = __expf(b.y), b2 = __expf(b.z), b3 = __expf(b.w);
    float sA = a0 + a1 + a2 + a3;
    float sB = b0 + b1 + b2 + b3;
    #pragma unroll
    for (int o = 8; o; o >>= 1) {
        sA += __shfl_xor_sync(0xffffffffu, sA, o);
        sB += __shfl_xor_sync(0xffffffffu, sB, o);
    }
    float iA = __fdividef(1.0f, sA);
    float iB = __fdividef(1.0f, sB);

    if (vA) {
        float* p = out + (size_t)diA * F_OUT + 4 * sl;
        asm volatile("red.global.add.v4.f32 [%0], {%1, %2, %3, %4};"
                     :: "l"(p), "f"(hA.x * a0 * iA), "f"(hA.y * a1 * iA),
                        "f"(hA.z * a2 * iA), "f"(hA.w * a3 * iA) : "memory");
    }
    if (vB) {
        float* p = out + (size_t)diB * F_OUT + 4 * sl;
        asm volatile("red.global.add.v4.f32 [%0], {%1, %2, %3, %4};"
                     :: "l"(p), "f"(hB.x * b0 * iB), "f"(hB.y * b1 * iB),
                        "f"(hB.z * b2 * iB), "f"(hB.w * b3 * iB) : "memory");
    }
}

// ---------------------------------------------------------------------------
extern "C" void kernel_launch(void* const* d_in, const int* in_sizes, int n_in,
                              void* d_out, int out_size) {
    const float* h    = (const float*)d_in[0];
    const float* ef   = (const float*)d_in[1];
    const float* w    = (const float*)d_in[2];
    const float* bias = (const float*)d_in[3];
    const int*   src  = (const int*)d_in[4];
    const int*   dst  = (const int*)d_in[5];
    float* out = (float*)d_out;

    int n_nodes = in_sizes[0] / F_IN;
    int n_edges = in_sizes[4];

    gemm_tc_kernel<<<(n_nodes + GR - 1) / GR, 256>>>(h, w, bias, out, n_nodes);

    int warps  = (n_edges + 3) / 4;
    int blocks = (warps * 32 + 255) / 256;
    edge_kernel<<<blocks, 256>>>(ef, src, dst, out, n_edges);
}

// round 13
// speedup vs baseline: 1.3105x; 1.0287x over previous
#include <cuda_runtime.h>
#include <cuda_bf16.h>
#include <cstdint>

#define F_IN 128
#define F_OUT 64
#define MAX_NODES 50000

// Scratch (no runtime allocation allowed)
__device__ float g_hw[(size_t)MAX_NODES * F_OUT]; // h @ (W0+W1), [N][64]

// ---------------------------------------------------------------------------
// TF32 / cp.async helpers
// ---------------------------------------------------------------------------
__device__ __forceinline__ unsigned cvt_tf32(float x) {
    unsigned r;
    asm("cvt.rna.tf32.f32 %0, %1;" : "=r"(r) : "f"(x));
    return r;
}

#define MMA_TF32(d, a0, a1, a2, a3, b0, b1)                                  \
    asm("mma.sync.aligned.m16n8k8.row.col.f32.tf32.tf32.f32 "                \
        "{%0,%1,%2,%3}, {%4,%5,%6,%7}, {%8,%9}, {%0,%1,%2,%3};"              \
        : "+f"(d[0]), "+f"(d[1]), "+f"(d[2]), "+f"(d[3])                     \
        : "r"(a0), "r"(a1), "r"(a2), "r"(a3), "r"(b0), "r"(b1))

__device__ __forceinline__ unsigned smem_u32(const void* p) {
    return (unsigned)__cvta_generic_to_shared(p);
}
// cp.async with src-size (0 -> zero-fill destination, no global read)
#define CP_ASYNC16Z(s, g, n) \
    asm volatile("cp.async.cg.shared.global [%0], [%1], 16, %2;" \
                 :: "r"(s), "l"(g), "r"(n))
#define CP_COMMIT() asm volatile("cp.async.commit_group;")
#define CP_WAIT0()  asm volatile("cp.async.wait_group 0;" ::: "memory")
#define CP_WAIT1()  asm volatile("cp.async.wait_group 1;" ::: "memory")

// ---------------------------------------------------------------------------
// Kernel 1: fused TF32 tensor-core GEMM + bias-init (3xTF32, fp32 accuracy)
//   g_hw[N,64] = h[N,128] @ (W0+W1) ;  out[N,64] = bias
// Round-8 shape (GR=64, 128 threads, 4 warps — measured best) with the A
// chunk staging converted to a cp.async double buffer: chunk k+1's DRAM
// fetch overlaps chunk k's compute. W staging stays synchronous (L2-hot
// 32KB, needs the sum + hi/lo split transform anyway).
// smem: 2*9.2 (A bufs) + 9.2 + 9.2 (W hi/lo) = 36.9 KB static.
// ---------------------------------------------------------------------------
#define GR 64
#define KC 32
#define NCHUNK (F_IN / KC)
#define HS_S 36
#define WS_S 72
__global__ void __launch_bounds__(128) gemm_tc_kernel(
        const float* __restrict__ h,
        const float* __restrict__ w,
        const float* __restrict__ bias,
        float* __restrict__ out,
        int n_nodes) {
    __shared__ __align__(16) float hs[2][GR][HS_S]; // 18.4 KB: A double buffer
    __shared__ __align__(16) float wh[KC][WS_S];    // 9.2 KB: Wsum hi [k][n]
    __shared__ __align__(16) float wl[KC][WS_S];    // 9.2 KB: Wsum lo [k][n]
    __shared__ __align__(16) float bs[F_OUT];

    int tid  = threadIdx.x;
    int lane = tid & 31;
    int warp = tid >> 5;
    int g = lane >> 2;
    int t = lane & 3;
    int row0 = blockIdx.x * GR;
    int wr0  = warp * 16;

    if (tid < F_OUT) bs[tid] = bias[tid];

    // ---- async A-chunk stage: 512 float4 (4 per thread), zero-fill OOB ----
    #define STAGE_A(buf, k0_)                                                  \
        do {                                                                   \
            _Pragma("unroll")                                                  \
            for (int i_ = tid; i_ < GR * (KC / 4); i_ += 128) {                \
                int r_ = i_ >> 3;                                              \
                int c_ = i_ & 7;                                               \
                int gr_ = row0 + r_;                                           \
                bool v_ = (gr_ < n_nodes);                                     \
                const char* gp_ = (const char*)(h +                            \
                    (size_t)(v_ ? gr_ : 0) * F_IN + (k0_)) + c_ * 16;          \
                CP_ASYNC16Z(smem_u32(&hs[buf][r_][4 * c_]), gp_, v_ ? 16 : 0); \
            }                                                                  \
        } while (0)

    STAGE_A(0, 0);
    CP_COMMIT();

    float acc[8][4];
    #pragma unroll
    for (int nt = 0; nt < 8; nt++)
        #pragma unroll
        for (int i = 0; i < 4; i++) acc[nt][i] = 0.0f;

    int pb = 0;
    #pragma unroll
    for (int chunk = 0; chunk < NCHUNK; chunk++) {
        int k0 = chunk * KC;

        // Prefetch next A chunk into the other buffer (deep async queue)
        if (chunk + 1 < NCHUNK) {
            STAGE_A(pb ^ 1, k0 + KC);
            CP_COMMIT();
        }

        // Synchronous W-chunk stage: wsum = W0+W1 split hi/lo (L2-hot, 512 f4)
        // (previous chunk's consumers finished at the syncthreads below)
        #pragma unroll
        for (int i = tid; i < KC * (F_OUT / 4); i += 128) {
            int k = i >> 4;
            int q = i & 15;
            const float4* w0 = (const float4*)(w + (size_t)(k0 + k) * F_OUT);
            const float4* w1 = (const float4*)(w + (size_t)F_IN * F_OUT + (size_t)(k0 + k) * F_OUT);
            float4 s0 = w0[q], s1 = w1[q];
            float s[4] = {s0.x + s1.x, s0.y + s1.y, s0.z + s1.z, s0.w + s1.w};
            #pragma unroll
            for (int j = 0; j < 4; j++) {
                float hi = __uint_as_float(cvt_tf32(s[j]));
                wh[k][4 * q + j] = hi;
                wl[k][4 * q + j] = s[j] - hi;
            }
        }

        // Current A buffer ready: if a prefetch is in flight allow 1 pending
        if (chunk + 1 < NCHUNK) { CP_WAIT1(); } else { CP_WAIT0(); }
        __syncthreads();   // A + W visible to all warps

        // Compute: 4 k-steps of 8
        #pragma unroll
        for (int ks = 0; ks < KC; ks += 8) {
            float af0 = hs[pb][wr0 + g][ks + t];
            float af1 = hs[pb][wr0 + g + 8][ks + t];
            float af2 = hs[pb][wr0 + g][ks + t + 4];
            float af3 = hs[pb][wr0 + g + 8][ks + t + 4];
            unsigned ah0 = cvt_tf32(af0), ah1 = cvt_tf32(af1);
            unsigned ah2 = cvt_tf32(af2), ah3 = cvt_tf32(af3);
            unsigned al0 = __float_as_uint(af0 - __uint_as_float(ah0));
            unsigned al1 = __float_as_uint(af1 - __uint_as_float(ah1));
            unsigned al2 = __float_as_uint(af2 - __uint_as_float(ah2));
            unsigned al3 = __float_as_uint(af3 - __uint_as_float(ah3));

            #pragma unroll
            for (int nt = 0; nt < 8; nt++) {
                int n = 8 * nt + g;
                unsigned bh0 = __float_as_uint(wh[ks + t][n]);
                unsigned bh1 = __float_as_uint(wh[ks + t + 4][n]);
                unsigned bl0 = __float_as_uint(wl[ks + t][n]);
                unsigned bl1 = __float_as_uint(wl[ks + t + 4][n]);
                MMA_TF32(acc[nt], ah0, ah1, ah2, ah3, bh0, bh1);
                MMA_TF32(acc[nt], ah0, ah1, ah2, ah3, bl0, bl1);
                MMA_TF32(acc[nt], al0, al1, al2, al3, bh0, bh1);
            }
        }
        __syncthreads();   // chunk consumed; W/A buffers may be overwritten
        pb ^= 1;
    }
    #undef STAGE_A

    int r1 = row0 + wr0 + g;
    int r2 = r1 + 8;
    #pragma unroll
    for (int nt = 0; nt < 8; nt++) {
        int c = 8 * nt + 2 * t;
        float2 bv = make_float2(bs[c], bs[c + 1]);
        if (r1 < n_nodes) {
            *(float2*)&g_hw[(size_t)r1 * F_OUT + c] = make_float2(acc[nt][0], acc[nt][1]);
            *(float2*)&out[(size_t)r1 * F_OUT + c] = bv;
        }
        if (r2 < n_nodes) {
            *(float2*)&g_hw[(size_t)r2 * F_OUT + c] = make_float2(acc[nt][2], acc[nt][3]);
            *(float2*)&out[(size_t)r2 * F_OUT + c] = bv;
        }
    }
}

// ---------------------------------------------------------------------------
// Kernel 2: edge phase — FROZEN at measured L2 roofline (round 8): 4 edges
// per warp, 2 per 16-lane group. L2 traffic ~615MB -> ~53us is the floor.
// ---------------------------------------------------------------------------
__global__ void edge_kernel(const float* __restrict__ ef,
                            const int* __restrict__ src,
                            const int* __restrict__ dst,
                            float* __restrict__ out,
                            int n_edges) {
    int gw   = (blockIdx.x * blockDim.x + threadIdx.x) >> 5;
    int lane = threadIdx.x & 31;
    int grp  = lane >> 4;
    int sl   = lane & 15;

    int eA = 4 * gw + grp;
    int eB = eA + 2;
    bool vA = (eA < n_edges), vB = (eB < n_edges);
    int ecA = vA ? eA : 0;
    int ecB = vB ? eB : 0;

    int siA = __ldg(src + ecA), diA = __ldg(dst + ecA);
    int siB = __ldg(src + ecB), diB = __ldg(dst + ecB);

    const float4* ef4 = (const float4*)ef;
    float4 a = __ldcs(ef4 + (size_t)ecA * (F_OUT / 4) + sl);
    float4 b = __ldcs(ef4 + (size_t)ecB * (F_OUT / 4) + sl);

    const float4* hw4 = (const float4*)g_hw;
    float4 hA = __ldg(hw4 + (size_t)siA * (F_OUT / 4) + sl);
    float4 hB = __ldg(hw4 + (size_t)siB * (F_OUT / 4) + sl);

    float a0 = __expf(a.x), a1 = __expf(a.y), a2 = __expf(a.z), a3 = __expf(a.w);
    float b0 = __expf(b.x), b1 = __expf(b.y), b2 = __expf(b.z), b3 = __expf(b.w);
    float sA = a0 + a1 + a2 + a3;
    float sB = b0 + b1 + b2 + b3;
    #pragma unroll
    for (int o = 8; o; o >>= 1) {
        sA += __shfl_xor_sync(0xffffffffu, sA, o);
        sB += __shfl_xor_sync(0xffffffffu, sB, o);
    }
    float iA = __fdividef(1.0f, sA);
    float iB = __fdividef(1.0f, sB);

    if (vA) {
        float* p = out + (size_t)diA * F_OUT + 4 * sl;
        asm volatile("red.global.add.v4.f32 [%0], {%1, %2, %3, %4};"
                     :: "l"(p), "f"(hA.x * a0 * iA), "f"(hA.y * a1 * iA),
                        "f"(hA.z * a2 * iA), "f"(hA.w * a3 * iA) : "memory");
    }
    if (vB) {
        float* p = out + (size_t)diB * F_OUT + 4 * sl;
        asm volatile("red.global.add.v4.f32 [%0], {%1, %2, %3, %4};"
                     :: "l"(p), "f"(hB.x * b0 * iB), "f"(hB.y * b1 * iB),
                        "f"(hB.z * b2 * iB), "f"(hB.w * b3 * iB) : "memory");
    }
}

// ---------------------------------------------------------------------------
extern "C" void kernel_launch(void* const* d_in, const int* in_sizes, int n_in,
                              void* d_out, int out_size) {
    const float* h    = (const float*)d_in[0];
    const float* ef   = (const float*)d_in[1];
    const float* w    = (const float*)d_in[2];
    const float* bias = (const float*)d_in[3];
    const int*   src  = (const int*)d_in[4];
    const int*   dst  = (const int*)d_in[5];
    float* out = (float*)d_out;

    int n_nodes = in_sizes[0] / F_IN;
    int n_edges = in_sizes[4];

    gemm_tc_kernel<<<(n_nodes + GR - 1) / GR, 128>>>(h, w, bias, out, n_nodes);

    int warps  = (n_edges + 3) / 4;
    int blocks = (warps * 32 + 255) / 256;
    edge_kernel<<<blocks, 256>>>(ef, src, dst, out, n_edges);
}

// round 14
// speedup vs baseline: 1.3449x; 1.0263x over previous
#include <cuda_runtime.h>
#include <cuda_bf16.h>
#include <cuda_fp16.h>
#include <cstdint>

#define F_IN 128
#define F_OUT 64
#define MAX_NODES 50000

// Scratch (no runtime allocation allowed): projected features in fp16.
// hw ~ N(0, 16^2); fp16 roundoff 2^-11 -> output rel err ~3e-4 << 1e-3.
__device__ __half g_hwh[(size_t)MAX_NODES * F_OUT];

// ---------------------------------------------------------------------------
// TF32 / cp.async helpers
// ---------------------------------------------------------------------------
__device__ __forceinline__ unsigned cvt_tf32(float x) {
    unsigned r;
    asm("cvt.rna.tf32.f32 %0, %1;" : "=r"(r) : "f"(x));
    return r;
}

#define MMA_TF32(d, a0, a1, a2, a3, b0, b1)                                  \
    asm("mma.sync.aligned.m16n8k8.row.col.f32.tf32.tf32.f32 "                \
        "{%0,%1,%2,%3}, {%4,%5,%6,%7}, {%8,%9}, {%0,%1,%2,%3};"              \
        : "+f"(d[0]), "+f"(d[1]), "+f"(d[2]), "+f"(d[3])                     \
        : "r"(a0), "r"(a1), "r"(a2), "r"(a3), "r"(b0), "r"(b1))

__device__ __forceinline__ unsigned smem_u32(const void* p) {
    return (unsigned)__cvta_generic_to_shared(p);
}
#define CP_ASYNC16Z(s, g, n) \
    asm volatile("cp.async.cg.shared.global [%0], [%1], 16, %2;" \
                 :: "r"(s), "l"(g), "r"(n))
#define CP_COMMIT() asm volatile("cp.async.commit_group;")
#define CP_WAIT0()  asm volatile("cp.async.wait_group 0;" ::: "memory")
#define CP_WAIT1()  asm volatile("cp.async.wait_group 1;" ::: "memory")

// ---------------------------------------------------------------------------
// Kernel 1: fused TF32 tensor-core GEMM + bias-init (3xTF32)
//   g_hwh[N,64] = fp16(h[N,128] @ (W0+W1)) ;  out[N,64] = bias
// Round-13 structure: GR=64/128 threads, cp.async double-buffered A,
// smem-staged W hi/lo split. Epilogue now packs accumulators to half2.
// ---------------------------------------------------------------------------
#define GR 64
#define KC 32
#define NCHUNK (F_IN / KC)
#define HS_S 36
#define WS_S 72
__global__ void __launch_bounds__(128) gemm_tc_kernel(
        const float* __restrict__ h,
        const float* __restrict__ w,
        const float* __restrict__ bias,
        float* __restrict__ out,
        int n_nodes) {
    __shared__ __align__(16) float hs[2][GR][HS_S]; // 18.4 KB: A double buffer
    __shared__ __align__(16) float wh[KC][WS_S];    // 9.2 KB: Wsum hi [k][n]
    __shared__ __align__(16) float wl[KC][WS_S];    // 9.2 KB: Wsum lo [k][n]
    __shared__ __align__(16) float bs[F_OUT];

    int tid  = threadIdx.x;
    int lane = tid & 31;
    int warp = tid >> 5;
    int g = lane >> 2;
    int t = lane & 3;
    int row0 = blockIdx.x * GR;
    int wr0  = warp * 16;

    if (tid < F_OUT) bs[tid] = bias[tid];

    #define STAGE_A(buf, k0_)                                                  \
        do {                                                                   \
            _Pragma("unroll")                                                  \
            for (int i_ = tid; i_ < GR * (KC / 4); i_ += 128) {                \
                int r_ = i_ >> 3;                                              \
                int c_ = i_ & 7;                                               \
                int gr_ = row0 + r_;                                           \
                bool v_ = (gr_ < n_nodes);                                     \
                const char* gp_ = (const char*)(h +                            \
                    (size_t)(v_ ? gr_ : 0) * F_IN + (k0_)) + c_ * 16;          \
                CP_ASYNC16Z(smem_u32(&hs[buf][r_][4 * c_]), gp_, v_ ? 16 : 0); \
            }                                                                  \
        } while (0)

    STAGE_A(0, 0);
    CP_COMMIT();

    float acc[8][4];
    #pragma unroll
    for (int nt = 0; nt < 8; nt++)
        #pragma unroll
        for (int i = 0; i < 4; i++) acc[nt][i] = 0.0f;

    int pb = 0;
    #pragma unroll
    for (int chunk = 0; chunk < NCHUNK; chunk++) {
        int k0 = chunk * KC;

        if (chunk + 1 < NCHUNK) {
            STAGE_A(pb ^ 1, k0 + KC);
            CP_COMMIT();
        }

        // Synchronous W-chunk stage (L2-hot): sum + tf32 hi/lo split
        #pragma unroll
        for (int i = tid; i < KC * (F_OUT / 4); i += 128) {
            int k = i >> 4;
            int q = i & 15;
            const float4* w0 = (const float4*)(w + (size_t)(k0 + k) * F_OUT);
            const float4* w1 = (const float4*)(w + (size_t)F_IN * F_OUT + (size_t)(k0 + k) * F_OUT);
            float4 s0 = w0[q], s1 = w1[q];
            float s[4] = {s0.x + s1.x, s0.y + s1.y, s0.z + s1.z, s0.w + s1.w};
            #pragma unroll
            for (int j = 0; j < 4; j++) {
                float hi = __uint_as_float(cvt_tf32(s[j]));
                wh[k][4 * q + j] = hi;
                wl[k][4 * q + j] = s[j] - hi;
            }
        }

        if (chunk + 1 < NCHUNK) { CP_WAIT1(); } else { CP_WAIT0(); }
        __syncthreads();

        #pragma unroll
        for (int ks = 0; ks < KC; ks += 8) {
            float af0 = hs[pb][wr0 + g][ks + t];
            float af1 = hs[pb][wr0 + g + 8][ks + t];
            float af2 = hs[pb][wr0 + g][ks + t + 4];
            float af3 = hs[pb][wr0 + g + 8][ks + t + 4];
            unsigned ah0 = cvt_tf32(af0), ah1 = cvt_tf32(af1);
            unsigned ah2 = cvt_tf32(af2), ah3 = cvt_tf32(af3);
            unsigned al0 = __float_as_uint(af0 - __uint_as_float(ah0));
            unsigned al1 = __float_as_uint(af1 - __uint_as_float(ah1));
            unsigned al2 = __float_as_uint(af2 - __uint_as_float(ah2));
            unsigned al3 = __float_as_uint(af3 - __uint_as_float(ah3));

            #pragma unroll
            for (int nt = 0; nt < 8; nt++) {
                int n = 8 * nt + g;
                unsigned bh0 = __float_as_uint(wh[ks + t][n]);
                unsigned bh1 = __float_as_uint(wh[ks + t + 4][n]);
                unsigned bl0 = __float_as_uint(wl[ks + t][n]);
                unsigned bl1 = __float_as_uint(wl[ks + t + 4][n]);
                MMA_TF32(acc[nt], ah0, ah1, ah2, ah3, bh0, bh1);
                MMA_TF32(acc[nt], ah0, ah1, ah2, ah3, bl0, bl1);
                MMA_TF32(acc[nt], al0, al1, al2, al3, bh0, bh1);
            }
        }
        __syncthreads();
        pb ^= 1;
    }
    #undef STAGE_A

    int r1 = row0 + wr0 + g;
    int r2 = r1 + 8;
    #pragma unroll
    for (int nt = 0; nt < 8; nt++) {
        int c = 8 * nt + 2 * t;           // even -> half2 stores 4B-aligned
        float2 bv = make_float2(bs[c], bs[c + 1]);
        if (r1 < n_nodes) {
            *(__half2*)&g_hwh[(size_t)r1 * F_OUT + c] =
                __floats2half2_rn(acc[nt][0], acc[nt][1]);
            *(float2*)&out[(size_t)r1 * F_OUT + c] = bv;
        }
        if (r2 < n_nodes) {
            *(__half2*)&g_hwh[(size_t)r2 * F_OUT + c] =
                __floats2half2_rn(acc[nt][2], acc[nt][3]);
            *(float2*)&out[(size_t)r2 * F_OUT + c] = bv;
        }
    }
}

// ---------------------------------------------------------------------------
// Edge phase core (shared by fast/general): 4 edges per warp, 2 per 16-lane
// group. Gather now fp16 (8B/lane, half the L1 wavefronts), softmax w/o
// max-sub, red.v4 into out[dst].
// ---------------------------------------------------------------------------
__device__ __forceinline__ void edge_pair(
        const float* __restrict__ ef, const int* __restrict__ src,
        const int* __restrict__ dst, float* __restrict__ out,
        int ecA, int ecB, bool vA, bool vB, int sl) {
    int siA = __ldg(src + ecA), diA = __ldg(dst + ecA);
    int siB = __ldg(src + ecB), diB = __ldg(dst + ecB);

    const float4* ef4 = (const float4*)ef;
    float4 a = __ldcs(ef4 + (size_t)ecA * (F_OUT / 4) + sl);
    float4 b = __ldcs(ef4 + (size_t)ecB * (F_OUT / 4) + sl);

    // fp16 gather: 4 halves = 8B per lane
    const uint2* hwv = (const uint2*)g_hwh;   // 4 halves per uint2, 16 per row
    uint2 rA = __ldg(hwv + (size_t)siA * 16 + sl);
    uint2 rB = __ldg(hwv + (size_t)siB * 16 + sl);
    float2 hA01 = __half22float2(*(const __half2*)&rA.x);
    float2 hA23 = __half22float2(*(const __half2*)&rA.y);
    float2 hB01 = __half22float2(*(const __half2*)&rB.x);
    float2 hB23 = __half22float2(*(const __half2*)&rB.y);

    float a0 = __expf(a.x), a1 = __expf(a.y), a2 = __expf(a.z), a3 = __expf(a.w);
    float b0 = __expf(b.x), b1 = __expf(b.y), b2 = __expf(b.z), b3 = __expf(b.w);
    float sA = a0 + a1 + a2 + a3;
    float sB = b0 + b1 + b2 + b3;
    #pragma unroll
    for (int o = 8; o; o >>= 1) {
        sA += __shfl_xor_sync(0xffffffffu, sA, o);
        sB += __shfl_xor_sync(0xffffffffu, sB, o);
    }
    float iA = __fdividef(1.0f, sA);
    float iB = __fdividef(1.0f, sB);

    if (vA) {
        float* p = out + (size_t)diA * F_OUT + 4 * sl;
        asm volatile("red.global.add.v4.f32 [%0], {%1, %2, %3, %4};"
                     :: "l"(p), "f"(hA01.x * a0 * iA), "f"(hA01.y * a1 * iA),
                        "f"(hA23.x * a2 * iA), "f"(hA23.y * a3 * iA) : "memory");
    }
    if (vB) {
        float* p = out + (size_t)diB * F_OUT + 4 * sl;
        asm volatile("red.global.add.v4.f32 [%0], {%1, %2, %3, %4};"
                     :: "l"(p), "f"(hB01.x * b0 * iB), "f"(hB01.y * b1 * iB),
                        "f"(hB23.x * b2 * iB), "f"(hB23.y * b3 * iB) : "memory");
    }
}

// Fast path: n_edges % 4 == 0 AND grid covers exactly -> zero bounds logic.
__global__ void edge_kernel_fast(const float* __restrict__ ef,
                                 const int* __restrict__ src,
                                 const int* __restrict__ dst,
                                 float* __restrict__ out) {
    int gw   = (blockIdx.x * blockDim.x + threadIdx.x) >> 5;
    int lane = threadIdx.x & 31;
    int grp  = lane >> 4;
    int sl   = lane & 15;
    int eA = 4 * gw + grp;
    edge_pair(ef, src, dst, out, eA, eA + 2, true, true, sl);
}

// General path: bounds-checked (clamped for convergence).
__global__ void edge_kernel(const float* __restrict__ ef,
                            const int* __restrict__ src,
                            const int* __restrict__ dst,
                            float* __restrict__ out,
                            int n_edges) {
    int gw   = (blockIdx.x * blockDim.x + threadIdx.x) >> 5;
    int lane = threadIdx.x & 31;
    int grp  = lane >> 4;
    int sl   = lane & 15;

    int eA = 4 * gw + grp;
    int eB = eA + 2;
    bool vA = (eA < n_edges), vB = (eB < n_edges);
    edge_pair(ef, src, dst, out, vA ? eA : 0, vB ? eB : 0, vA, vB, sl);
}

// ---------------------------------------------------------------------------
extern "C" void kernel_launch(void* const* d_in, const int* in_sizes, int n_in,
                              void* d_out, int out_size) {
    const float* h    = (const float*)d_in[0];
    const float* ef   = (const float*)d_in[1];
    const float* w    = (const float*)d_in[2];
    const float* bias = (const float*)d_in[3];
    const int*   src  = (const int*)d_in[4];
    const int*   dst  = (const int*)d_in[5];
    float* out = (float*)d_out;

    int n_nodes = in_sizes[0] / F_IN;
    int n_edges = in_sizes[4];

    gemm_tc_kernel<<<(n_nodes + GR - 1) / GR, 128>>>(h, w, bias, out, n_nodes);

    if (n_edges % 4 == 0 && (n_edges / 4) % 8 == 0) {
        // exact cover: warps = n_edges/4, 8 warps per block
        edge_kernel_fast<<<n_edges / 32, 256>>>(ef, src, dst, out);
    } else {
        int warps  = (n_edges + 3) / 4;
        int blocks = (warps * 32 + 255) / 256;
        edge_kernel<<<blocks, 256>>>(ef, src, dst, out, n_edges);
    }
}

// round 15
// speedup vs baseline: 1.4801x; 1.1005x over previous
#include <cuda_runtime.h>
#include <cuda_bf16.h>
#include <cuda_fp16.h>
#include <cstdint>

#define F_IN 128
#define F_OUT 64
#define MAX_NODES 50000

// Scratch (no runtime allocation allowed): projected features in fp16.
__device__ __half g_hwh[(size_t)MAX_NODES * F_OUT];

// ---------------------------------------------------------------------------
// TF32 / cp.async helpers
// ---------------------------------------------------------------------------
__device__ __forceinline__ unsigned cvt_tf32(float x) {
    unsigned r;
    asm("cvt.rna.tf32.f32 %0, %1;" : "=r"(r) : "f"(x));
    return r;
}

#define MMA_TF32(d, a0, a1, a2, a3, b0, b1)                                  \
    asm("mma.sync.aligned.m16n8k8.row.col.f32.tf32.tf32.f32 "                \
        "{%0,%1,%2,%3}, {%4,%5,%6,%7}, {%8,%9}, {%0,%1,%2,%3};"              \
        : "+f"(d[0]), "+f"(d[1]), "+f"(d[2]), "+f"(d[3])                     \
        : "r"(a0), "r"(a1), "r"(a2), "r"(a3), "r"(b0), "r"(b1))

__device__ __forceinline__ unsigned smem_u32(const void* p) {
    return (unsigned)__cvta_generic_to_shared(p);
}
#define CP_ASYNC16Z(s, g, n) \
    asm volatile("cp.async.cg.shared.global [%0], [%1], 16, %2;" \
                 :: "r"(s), "l"(g), "r"(n))
#define CP_COMMIT() asm volatile("cp.async.commit_group;")
#define CP_WAIT0()  asm volatile("cp.async.wait_group 0;" ::: "memory")
#define CP_WAIT1()  asm volatile("cp.async.wait_group 1;" ::: "memory")

// ---------------------------------------------------------------------------
// Kernel 1: fused TF32 tensor-core GEMM + bias-init — SINGLE-PASS TF32.
//   g_hwh[N,64] = fp16(h[N,128] @ (W0+W1)) ;  out[N,64] = bias
// Error budget: tf32 1-pass (~4e-4) + fp16 store (~1.7e-4) ≈ 4.4e-4 < 1e-3.
// Structure: GR=64/128 threads, cp.async double-buffered A, smem W (tf32-
// rounded sum, no hi/lo split). smem 27.6 KB.
// ---------------------------------------------------------------------------
#define GR 64
#define KC 32
#define NCHUNK (F_IN / KC)
#define HS_S 36
#define WS_S 72
__global__ void __launch_bounds__(128) gemm_tc_kernel(
        const float* __restrict__ h,
        const float* __restrict__ w,
        const float* __restrict__ bias,
        float* __restrict__ out,
        int n_nodes) {
    __shared__ __align__(16) float hs[2][GR][HS_S]; // 18.4 KB: A double buffer
    __shared__ __align__(16) float ws[KC][WS_S];    // 9.2 KB: tf32(W0+W1) [k][n]
    __shared__ __align__(16) float bs[F_OUT];

    int tid  = threadIdx.x;
    int lane = tid & 31;
    int warp = tid >> 5;
    int g = lane >> 2;
    int t = lane & 3;
    int row0 = blockIdx.x * GR;
    int wr0  = warp * 16;

    if (tid < F_OUT) bs[tid] = bias[tid];

    #define STAGE_A(buf, k0_)                                                  \
        do {                                                                   \
            _Pragma("unroll")                                                  \
            for (int i_ = tid; i_ < GR * (KC / 4); i_ += 128) {                \
                int r_ = i_ >> 3;                                              \
                int c_ = i_ & 7;                                               \
                int gr_ = row0 + r_;                                           \
                bool v_ = (gr_ < n_nodes);                                     \
                const char* gp_ = (const char*)(h +                            \
                    (size_t)(v_ ? gr_ : 0) * F_IN + (k0_)) + c_ * 16;          \
                CP_ASYNC16Z(smem_u32(&hs[buf][r_][4 * c_]), gp_, v_ ? 16 : 0); \
            }                                                                  \
        } while (0)

    STAGE_A(0, 0);
    CP_COMMIT();

    float acc[8][4];
    #pragma unroll
    for (int nt = 0; nt < 8; nt++)
        #pragma unroll
        for (int i = 0; i < 4; i++) acc[nt][i] = 0.0f;

    int pb = 0;
    #pragma unroll
    for (int chunk = 0; chunk < NCHUNK; chunk++) {
        int k0 = chunk * KC;

        if (chunk + 1 < NCHUNK) {
            STAGE_A(pb ^ 1, k0 + KC);
            CP_COMMIT();
        }

        // Synchronous W-chunk stage (L2-hot): sum, tf32-round, store
        #pragma unroll
        for (int i = tid; i < KC * (F_OUT / 4); i += 128) {
            int k = i >> 4;
            int q = i & 15;
            const float4* w0 = (const float4*)(w + (size_t)(k0 + k) * F_OUT);
            const float4* w1 = (const float4*)(w + (size_t)F_IN * F_OUT + (size_t)(k0 + k) * F_OUT);
            float4 s0 = w0[q], s1 = w1[q];
            ws[k][4 * q + 0] = __uint_as_float(cvt_tf32(s0.x + s1.x));
            ws[k][4 * q + 1] = __uint_as_float(cvt_tf32(s0.y + s1.y));
            ws[k][4 * q + 2] = __uint_as_float(cvt_tf32(s0.z + s1.z));
            ws[k][4 * q + 3] = __uint_as_float(cvt_tf32(s0.w + s1.w));
        }

        if (chunk + 1 < NCHUNK) { CP_WAIT1(); } else { CP_WAIT0(); }
        __syncthreads();

        #pragma unroll
        for (int ks = 0; ks < KC; ks += 8) {
            unsigned ah0 = cvt_tf32(hs[pb][wr0 + g][ks + t]);
            unsigned ah1 = cvt_tf32(hs[pb][wr0 + g + 8][ks + t]);
            unsigned ah2 = cvt_tf32(hs[pb][wr0 + g][ks + t + 4]);
            unsigned ah3 = cvt_tf32(hs[pb][wr0 + g + 8][ks + t + 4]);

            #pragma unroll
            for (int nt = 0; nt < 8; nt++) {
                int n = 8 * nt + g;
                unsigned bh0 = __float_as_uint(ws[ks + t][n]);
                unsigned bh1 = __float_as_uint(ws[ks + t + 4][n]);
                MMA_TF32(acc[nt], ah0, ah1, ah2, ah3, bh0, bh1);
            }
        }
        __syncthreads();
        pb ^= 1;
    }
    #undef STAGE_A

    int r1 = row0 + wr0 + g;
    int r2 = r1 + 8;
    #pragma unroll
    for (int nt = 0; nt < 8; nt++) {
        int c = 8 * nt + 2 * t;
        float2 bv = make_float2(bs[c], bs[c + 1]);
        if (r1 < n_nodes) {
            *(__half2*)&g_hwh[(size_t)r1 * F_OUT + c] =
                __floats2half2_rn(acc[nt][0], acc[nt][1]);
            *(float2*)&out[(size_t)r1 * F_OUT + c] = bv;
        }
        if (r2 < n_nodes) {
            *(__half2*)&g_hwh[(size_t)r2 * F_OUT + c] =
                __floats2half2_rn(acc[nt][2], acc[nt][3]);
            *(float2*)&out[(size_t)r2 * F_OUT + c] = bv;
        }
    }
}

// ---------------------------------------------------------------------------
// Edge phase core: 4 edges per warp, 2 per 16-lane group, fp16 gather.
// (Measured optimum — frozen since round 14.)
// ---------------------------------------------------------------------------
__device__ __forceinline__ void edge_pair(
        const float* __restrict__ ef, const int* __restrict__ src,
        const int* __restrict__ dst, float* __restrict__ out,
        int ecA, int ecB, bool vA, bool vB, int sl) {
    int siA = __ldg(src + ecA), diA = __ldg(dst + ecA);
    int siB = __ldg(src + ecB), diB = __ldg(dst + ecB);

    const float4* ef4 = (const float4*)ef;
    float4 a = __ldcs(ef4 + (size_t)ecA * (F_OUT / 4) + sl);
    float4 b = __ldcs(ef4 + (size_t)ecB * (F_OUT / 4) + sl);

    const uint2* hwv = (const uint2*)g_hwh;
    uint2 rA = __ldg(hwv + (size_t)siA * 16 + sl);
    uint2 rB = __ldg(hwv + (size_t)siB * 16 + sl);
    float2 hA01 = __half22float2(*(const __half2*)&rA.x);
    float2 hA23 = __half22float2(*(const __half2*)&rA.y);
    float2 hB01 = __half22float2(*(const __half2*)&rB.x);
    float2 hB23 = __half22float2(*(const __half2*)&rB.y);

    float a0 = __expf(a.x), a1 = __expf(a.y), a2 = __expf(a.z), a3 = __expf(a.w);
    float b0 = __expf(b.x), b1 = __expf(b.y), b2 = __expf(b.z), b3 = __expf(b.w);
    float sA = a0 + a1 + a2 + a3;
    float sB = b0 + b1 + b2 + b3;
    #pragma unroll
    for (int o = 8; o; o >>= 1) {
        sA += __shfl_xor_sync(0xffffffffu, sA, o);
        sB += __shfl_xor_sync(0xffffffffu, sB, o);
    }
    float iA = __fdividef(1.0f, sA);
    float iB = __fdividef(1.0f, sB);

    if (vA) {
        float* p = out + (size_t)diA * F_OUT + 4 * sl;
        asm volatile("red.global.add.v4.f32 [%0], {%1, %2, %3, %4};"
                     :: "l"(p), "f"(hA01.x * a0 * iA), "f"(hA01.y * a1 * iA),
                        "f"(hA23.x * a2 * iA), "f"(hA23.y * a3 * iA) : "memory");
    }
    if (vB) {
        float* p = out + (size_t)diB * F_OUT + 4 * sl;
        asm volatile("red.global.add.v4.f32 [%0], {%1, %2, %3, %4};"
                     :: "l"(p), "f"(hB01.x * b0 * iB), "f"(hB01.y * b1 * iB),
                        "f"(hB23.x * b2 * iB), "f"(hB23.y * b3 * iB) : "memory");
    }
}

// Fast path: exact grid cover, zero bounds logic.
__global__ void edge_kernel_fast(const float* __restrict__ ef,
                                 const int* __restrict__ src,
                                 const int* __restrict__ dst,
                                 float* __restrict__ out) {
    int gw   = (blockIdx.x * blockDim.x + threadIdx.x) >> 5;
    int lane = threadIdx.x & 31;
    int grp  = lane >> 4;
    int sl   = lane & 15;
    int eA = 4 * gw + grp;
    edge_pair(ef, src, dst, out, eA, eA + 2, true, true, sl);
}

// General path: bounds-checked (clamped for convergence).
__global__ void edge_kernel(const float* __restrict__ ef,
                            const int* __restrict__ src,
                            const int* __restrict__ dst,
                            float* __restrict__ out,
                            int n_edges) {
    int gw   = (blockIdx.x * blockDim.x + threadIdx.x) >> 5;
    int lane = threadIdx.x & 31;
    int grp  = lane >> 4;
    int sl   = lane & 15;

    int eA = 4 * gw + grp;
    int eB = eA + 2;
    bool vA = (eA < n_edges), vB = (eB < n_edges);
    edge_pair(ef, src, dst, out, vA ? eA : 0, vB ? eB : 0, vA, vB, sl);
}

// ---------------------------------------------------------------------------
extern "C" void kernel_launch(void* const* d_in, const int* in_sizes, int n_in,
                              void* d_out, int out_size) {
    const float* h    = (const float*)d_in[0];
    const float* ef   = (const float*)d_in[1];
    const float* w    = (const float*)d_in[2];
    const float* bias = (const float*)d_in[3];
    const int*   src  = (const int*)d_in[4];
    const int*   dst  = (const int*)d_in[5];
    float* out = (float*)d_out;

    int n_nodes = in_sizes[0] / F_IN;
    int n_edges = in_sizes[4];

    gemm_tc_kernel<<<(n_nodes + GR - 1) / GR, 128>>>(h, w, bias, out, n_nodes);

    if (n_edges % 4 == 0 && (n_edges / 4) % 8 == 0) {
        edge_kernel_fast<<<n_edges / 32, 256>>>(ef, src, dst, out);
    } else {
        int warps  = (n_edges + 3) / 4;
        int blocks = (warps * 32 + 255) / 256;
        edge_kernel<<<blocks, 256>>>(ef, src, dst, out, n_edges);
    }
}